// round 15
// baseline (speedup 1.0000x reference)
#include <cuda_runtime.h>
#include <cstdint>

// Problem: x (8,512,64,64) f32, mask (64,64) i32, out (8,768,64,64) f32
#define HW      4096
#define BATCH   8
#define CIN     512
#define C2      256
#define COUT    768

#define N_A     1024               // argmax CTAs (4 rows each) + copy plane=bid
#define N_B     (BATCH * C2)       // 2048 shift CTAs
#define N_C     3072               // pure copy CTAs (planes 1024..4095)
#define GRID_TOTAL (N_A + N_B + N_C)

// Scratch (allocation-free rule: __device__ globals)
__device__ int g_sidx[HW];         // flag[i] ? nb[i] : -1
__device__ int g_done    = 0;      // rows published (A CTAs add 4 each)
__device__ int g_arrived = 0;      // shift CTAs past the spin

// ---------------------------------------------------------------------------
// threefry2x32 with key (0, 42), counters (x0=0, x1=c). JAX partitionable path:
// bits[i] = o0 ^ o1 with counter = i. ks = [0, 42, 0 ^ 42 ^ 0x1BD11BDA].
// Returns the 23-bit monotone proxy for uniform(float).
// ---------------------------------------------------------------------------
__device__ __forceinline__ unsigned threefry_bits(unsigned c) {
    const unsigned ks1 = 42u;
    const unsigned ks2 = 0x1BD11BDAu ^ 42u;   // 0x1BD11BF0
    unsigned x0 = 0u;          // counts_hi + ks0
    unsigned x1 = c + ks1;     // counts_lo + ks1
#define TF_RND(r) { x0 += x1; x1 = __funnelshift_l(x1, x1, (r)); x1 ^= x0; }
    TF_RND(13) TF_RND(15) TF_RND(26) TF_RND(6)
    x0 += ks1;  x1 += ks2 + 1u;
    TF_RND(17) TF_RND(29) TF_RND(16) TF_RND(24)
    x0 += ks2;  x1 += 0u  + 2u;
    TF_RND(13) TF_RND(15) TF_RND(26) TF_RND(6)
    x0 += 0u;   x1 += ks1 + 3u;
    TF_RND(17) TF_RND(29) TF_RND(16) TF_RND(24)
    x0 += ks1;  x1 += ks2 + 4u;
    TF_RND(13) TF_RND(15) TF_RND(26) TF_RND(6)
    x0 += ks2;  x1 += 0u  + 5u;
#undef TF_RND
    return (x0 ^ x1) >> 9;
}

// ---------------------------------------------------------------------------
// Copy of plane p: out[b, ch] = x[b, ch], ch < 512.
// ---------------------------------------------------------------------------
__device__ __forceinline__ void do_copy(int p, int tid,
                                        const float* __restrict__ x,
                                        float* __restrict__ out) {
    const int b  = p >> 9;             // /512
    const int ch = p & 511;
    const float4* __restrict__ src =
        (const float4*)(x + ((size_t)b * CIN + ch) * HW);
    float4* __restrict__ dst =
        (float4*)(out + ((size_t)b * COUT + ch) * HW);
#pragma unroll
    for (int k = 0; k < 4; k++) {
        int idx = tid + k * 256;
        dst[idx] = src[idx];
    }
}

// ---------------------------------------------------------------------------
__global__ void __launch_bounds__(256) fused_kernel(const float* __restrict__ x,
                                                    const int*   __restrict__ mask,
                                                    float*       __restrict__ out) {
    const int bid = blockIdx.x;
    const int tid = threadIdx.x;

    __shared__ union {
        struct {
            unsigned short scols[HW];  // compacted columns (ascending), 8 KB
            int wred[8];
            unsigned long long wmax[8];
        } a;
        float plane[HW];               // shift CTAs: staged source plane, 16 KB
    } sm;

    if (bid < N_A) {
        // =========== A: argmax for rows [4*bid, 4*bid+4), then copy ===========
        // ---- compaction ONCE (column set is row-independent) ----
        const int lane = tid & 31;
        const int warp = tid >> 5;
        unsigned flags = 0;
        const int4* m4 = (const int4*)mask;
#pragma unroll
        for (int k = 0; k < 4; k++) {
            int4 v = m4[tid * 4 + k];
            if (v.x <= 0) flags |= 1u << (k * 4 + 0);
            if (v.y <= 0) flags |= 1u << (k * 4 + 1);
            if (v.z <= 0) flags |= 1u << (k * 4 + 2);
            if (v.w <= 0) flags |= 1u << (k * 4 + 3);
        }
        const int cnt = __popc(flags);
        int inc = cnt;
#pragma unroll
        for (int o = 1; o < 32; o <<= 1) {
            int v = __shfl_up_sync(0xFFFFFFFFu, inc, o);
            if (lane >= o) inc += v;
        }
        if (lane == 31) sm.a.wred[warp] = inc;
        __syncthreads();
        if (tid < 32) {
            int v = (tid < 8) ? sm.a.wred[tid] : 0;
#pragma unroll
            for (int o = 1; o < 8; o <<= 1) {
                int u = __shfl_up_sync(0xFFFFFFFFu, v, o);
                if (lane >= o) v += u;
            }
            if (tid < 8) sm.a.wred[tid] = v;   // inclusive warp totals
        }
        __syncthreads();
        {
            int pos = inc - cnt + (warp ? sm.a.wred[warp - 1] : 0);
            const unsigned short base = (unsigned short)(tid * 16);
#pragma unroll
            for (int k = 0; k < 16; k++) {
                if (flags & (1u << k)) sm.a.scols[pos++] = base + (unsigned short)k;
            }
        }
        __syncthreads();
        const int m = sm.a.wred[7];

        // ---- 4 rows, reusing the compacted column list ----
#pragma unroll 1
        for (int r4 = 0; r4 < 4; r4++) {
            const int row = bid * 4 + r4;
            if (mask[row] > 0) {
                const unsigned rowbase = (unsigned)row * (unsigned)HW;
                unsigned bv = 0u;
                int bj = HW - 1;     // phantom: loses to every real candidate

                int t = tid;
                for (; t + 256 < m; t += 512) {   // two independent chains
                    int j0 = sm.a.scols[t];
                    int j1 = sm.a.scols[t + 256];
                    unsigned v0 = threefry_bits(rowbase + (unsigned)j0);
                    unsigned v1 = threefry_bits(rowbase + (unsigned)j1);
                    if (v0 > bv) { bv = v0; bj = j0; }  // j0 < j1: order kept
                    if (v1 > bv) { bv = v1; bj = j1; }
                }
                if (t < m) {
                    int j = sm.a.scols[t];
                    unsigned v = threefry_bits(rowbase + (unsigned)j);
                    if (v > bv) { bv = v; bj = j; }
                }

                unsigned long long key =
                    ((unsigned long long)bv << 12) | (unsigned)(HW - 1 - bj);
#pragma unroll
                for (int o = 16; o > 0; o >>= 1) {
                    unsigned long long other = __shfl_xor_sync(0xFFFFFFFFu, key, o);
                    if (other > key) key = other;
                }
                if (lane == 0) sm.a.wmax[warp] = key;
                __syncthreads();
                if (tid < 32) {
                    unsigned long long k2 = (tid < 8) ? sm.a.wmax[tid] : 0ull;
#pragma unroll
                    for (int o = 4; o > 0; o >>= 1) {
                        unsigned long long other = __shfl_xor_sync(0xFFFFFFFFu, k2, o);
                        if (other > k2) k2 = other;
                    }
                    if (tid == 0)
                        g_sidx[row] = (m == 0) ? 0 : (HW - 1 - (int)(k2 & 0xFFFu));
                }
            } else {
                if (tid == 0) g_sidx[row] = -1;
            }
            __syncthreads();   // protect wmax reuse across rows
        }
        if (tid == 0) {
            __threadfence();
            atomicAdd(&g_done, 4);
        }

        // ---- copy plane = bid (planes 0..1023) ----
        do_copy(bid, tid, x, out);

    } else if (bid < N_A + N_B) {
        // =========== B: shift plane (dispatched right after argmax) ===========
        const int p  = bid - N_A;            // 0..2047
        const int b  = p >> 8;
        const int cc = p & 255;

        const float* __restrict__ src = x + ((size_t)b * CIN + C2 + cc) * HW;

        // stage source plane into smem (coalesced), independent of g_sidx
        {
            const float4* __restrict__ s4 = (const float4*)src;
            float4* __restrict__ p4 = (float4*)sm.plane;
#pragma unroll
            for (int k = 0; k < 4; k++) {
                int idx = tid + k * 256;
                p4[idx] = s4[idx];
            }
        }

        if (tid == 0) {
            // spin until all 4096 rows are published (A CTAs only).
            while (atomicAdd(&g_done, 0) != HW) __nanosleep(100);
            // last of the N_B shift CTAs to pass resets for next graph replay.
            int a = atomicAdd(&g_arrived, 1);
            if (a == N_B - 1) {
                atomicExch(&g_done, 0);
                atomicExch(&g_arrived, 0);
            }
        }
        __syncthreads();   // plane staged + sidx published

        float4* __restrict__ dst =
            (float4*)(out + ((size_t)b * COUT + CIN + cc) * HW);
        const int4* __restrict__ sidx4 = (const int4*)g_sidx;
#pragma unroll
        for (int k = 0; k < 4; k++) {
            int idx = tid + k * 256;
            int4 s = sidx4[idx];
            float4 v;
            v.x = (s.x >= 0) ? sm.plane[s.x] : 0.0f;
            v.y = (s.y >= 0) ? sm.plane[s.y] : 0.0f;
            v.z = (s.z >= 0) ? sm.plane[s.z] : 0.0f;
            v.w = (s.w >= 0) ? sm.plane[s.w] : 0.0f;
            dst[idx] = v;
        }
    } else {
        // =========== C: pure copy (planes 1024..4095) ===========
        do_copy(bid - N_A - N_B + N_A, tid, x, out);   // plane = bid - 3072 + 1024
    }
}

// ---------------------------------------------------------------------------
extern "C" void kernel_launch(void* const* d_in, const int* in_sizes, int n_in,
                              void* d_out, int out_size) {
    const float* x    = (const float*)d_in[0];   // (8,512,64,64) f32
    const int*   mask = (const int*)d_in[1];     // (64,64) i32
    float* out = (float*)d_out;                  // (8,768,64,64) f32
    (void)in_sizes; (void)n_in; (void)out_size;

    fused_kernel<<<GRID_TOTAL, 256>>>(x, mask, out);
}

// round 16
// speedup vs baseline: 1.1420x; 1.1420x over previous
#include <cuda_runtime.h>
#include <cstdint>

// Problem: x (8,512,64,64) f32, mask (64,64) i32, out (8,768,64,64) f32
#define HW      4096
#define BATCH   8
#define CIN     512
#define C2      256
#define COUT    768

#define N_G1    2048               // warp-split: argmax 2 rows + copy plane=bid
#define N_G2    2048               // pure copy (planes 2048..4095)
#define N_G3    (BATCH * C2)       // 2048 shift CTAs (dispatched LAST)
#define GRID_TOTAL (N_G1 + N_G2 + N_G3)

// Scratch (allocation-free rule: __device__ globals)
__device__ int g_sidx[HW];         // flag[i] ? nb[i] : -1
__device__ int g_done    = 0;      // rows published (G1 CTAs add 2 each)
__device__ int g_arrived = 0;      // shift CTAs past the spin

// ---------------------------------------------------------------------------
// threefry2x32 with key (0, 42), counters (x0=0, x1=c). JAX partitionable path:
// bits[i] = o0 ^ o1 with counter = i. ks = [0, 42, 0 ^ 42 ^ 0x1BD11BDA].
// Returns the 23-bit monotone proxy for uniform(float).
// ---------------------------------------------------------------------------
__device__ __forceinline__ unsigned threefry_bits(unsigned c) {
    const unsigned ks1 = 42u;
    const unsigned ks2 = 0x1BD11BDAu ^ 42u;   // 0x1BD11BF0
    unsigned x0 = 0u;          // counts_hi + ks0
    unsigned x1 = c + ks1;     // counts_lo + ks1
#define TF_RND(r) { x0 += x1; x1 = __funnelshift_l(x1, x1, (r)); x1 ^= x0; }
    TF_RND(13) TF_RND(15) TF_RND(26) TF_RND(6)
    x0 += ks1;  x1 += ks2 + 1u;
    TF_RND(17) TF_RND(29) TF_RND(16) TF_RND(24)
    x0 += ks2;  x1 += 0u  + 2u;
    TF_RND(13) TF_RND(15) TF_RND(26) TF_RND(6)
    x0 += 0u;   x1 += ks1 + 3u;
    TF_RND(17) TF_RND(29) TF_RND(16) TF_RND(24)
    x0 += ks1;  x1 += ks2 + 4u;
    TF_RND(13) TF_RND(15) TF_RND(26) TF_RND(6)
    x0 += ks2;  x1 += 0u  + 5u;
#undef TF_RND
    return (x0 ^ x1) >> 9;
}

#define BAR_ARG(n) asm volatile("bar.sync 1, %0;" :: "r"(n) : "memory")

// ---------------------------------------------------------------------------
__global__ void __launch_bounds__(256) fused_kernel(const float* __restrict__ x,
                                                    const int*   __restrict__ mask,
                                                    float*       __restrict__ out) {
    const int bid = blockIdx.x;
    const int tid = threadIdx.x;

    __shared__ union {
        struct {
            unsigned short scols[HW];  // compacted columns (ascending), 8 KB
            int wred[4];
            unsigned long long wmax[4];
        } a;
        float plane[HW];               // shift CTAs: staged source plane, 16 KB
    } sm;

    if (bid < N_G1) {
        // ======== G1: warps 0-3 argmax rows {2bid, 2bid+1}; warps 4-7 copy ====
        if (tid < 128) {
            // ---------------- argmax half (128 threads) ----------------
            const int lane = tid & 31;
            const int warp = tid >> 5;         // 0..3

            // compaction once: thread owns cols [32t, 32t+32)
            unsigned flags = 0;
            const int4* m4 = (const int4*)mask;
#pragma unroll
            for (int k = 0; k < 8; k++) {
                int4 v = m4[tid * 8 + k];
                if (v.x <= 0) flags |= 1u << (k * 4 + 0);
                if (v.y <= 0) flags |= 1u << (k * 4 + 1);
                if (v.z <= 0) flags |= 1u << (k * 4 + 2);
                if (v.w <= 0) flags |= 1u << (k * 4 + 3);
            }
            const int cnt = __popc(flags);
            int inc = cnt;
#pragma unroll
            for (int o = 1; o < 32; o <<= 1) {
                int v = __shfl_up_sync(0xFFFFFFFFu, inc, o);
                if (lane >= o) inc += v;
            }
            if (lane == 31) sm.a.wred[warp] = inc;
            BAR_ARG(128);
            // prefix of warp totals (4 entries) read directly
            int wpre = 0;
#pragma unroll
            for (int w = 0; w < 3; w++) if (warp > w) wpre += sm.a.wred[w];
            const int m = sm.a.wred[0] + sm.a.wred[1] + sm.a.wred[2] + sm.a.wred[3];
            {
                int pos = wpre + inc - cnt;
                const unsigned short base = (unsigned short)(tid * 32);
#pragma unroll
                for (int k = 0; k < 32; k++) {
                    if (flags & (1u << k)) sm.a.scols[pos++] = base + (unsigned short)k;
                }
            }
            BAR_ARG(128);

            // two rows, reusing the compacted list
#pragma unroll 1
            for (int r2 = 0; r2 < 2; r2++) {
                const int row = bid * 2 + r2;
                if (mask[row] > 0) {
                    const unsigned rowbase = (unsigned)row * (unsigned)HW;
                    unsigned bv = 0u;
                    int bj = HW - 1;   // phantom: loses to every real candidate

                    int t = tid;
                    for (; t + 128 < m; t += 256) {   // two independent chains
                        int j0 = sm.a.scols[t];
                        int j1 = sm.a.scols[t + 128];
                        unsigned v0 = threefry_bits(rowbase + (unsigned)j0);
                        unsigned v1 = threefry_bits(rowbase + (unsigned)j1);
                        if (v0 > bv) { bv = v0; bj = j0; }
                        if (v1 > bv) { bv = v1; bj = j1; }
                    }
                    if (t < m) {
                        int j = sm.a.scols[t];
                        unsigned v = threefry_bits(rowbase + (unsigned)j);
                        if (v > bv) { bv = v; bj = j; }
                    }

                    unsigned long long key =
                        ((unsigned long long)bv << 12) | (unsigned)(HW - 1 - bj);
#pragma unroll
                    for (int o = 16; o > 0; o >>= 1) {
                        unsigned long long other = __shfl_xor_sync(0xFFFFFFFFu, key, o);
                        if (other > key) key = other;
                    }
                    if (lane == 0) sm.a.wmax[warp] = key;
                    BAR_ARG(128);
                    if (tid == 0) {
                        unsigned long long k2 = sm.a.wmax[0];
                        if (sm.a.wmax[1] > k2) k2 = sm.a.wmax[1];
                        if (sm.a.wmax[2] > k2) k2 = sm.a.wmax[2];
                        if (sm.a.wmax[3] > k2) k2 = sm.a.wmax[3];
                        g_sidx[row] = (m == 0) ? 0 : (HW - 1 - (int)(k2 & 0xFFFu));
                    }
                    BAR_ARG(128);   // protect wmax reuse across rows
                } else {
                    if (tid == 0) g_sidx[row] = -1;
                }
            }
            if (tid == 0) {
                __threadfence();
                atomicAdd(&g_done, 2);
            }
        } else {
            // ---------------- copy half (128 threads): plane = bid ----------
            const int t128 = tid - 128;
            const int b  = bid >> 9;           // 0..3
            const int ch = bid & 511;
            const float4* __restrict__ src =
                (const float4*)(x + ((size_t)b * CIN + ch) * HW);
            float4* __restrict__ dst =
                (float4*)(out + ((size_t)b * COUT + ch) * HW);
#pragma unroll
            for (int k = 0; k < 8; k++) {
                int idx = t128 + k * 128;
                dst[idx] = src[idx];
            }
        }
    } else if (bid < N_G1 + N_G2) {
        // =========== G2: pure copy, planes 2048..4095 ===========
        const int p  = bid;                    // == 2048 + (bid - 2048)
        const int b  = p >> 9;                 // 4..7
        const int ch = p & 511;
        const float4* __restrict__ src =
            (const float4*)(x + ((size_t)b * CIN + ch) * HW);
        float4* __restrict__ dst =
            (float4*)(out + ((size_t)b * COUT + ch) * HW);
#pragma unroll
        for (int k = 0; k < 4; k++) {
            int idx = tid + k * 256;
            dst[idx] = src[idx];
        }
    } else {
        // =========== G3: shift plane (dispatched last -> no real wait) =======
        const int p  = bid - N_G1 - N_G2;      // 0..2047
        const int b  = p >> 8;
        const int cc = p & 255;

        const float* __restrict__ src = x + ((size_t)b * CIN + C2 + cc) * HW;

        // stage source plane into smem (coalesced), independent of g_sidx
        {
            const float4* __restrict__ s4 = (const float4*)src;
            float4* __restrict__ p4 = (float4*)sm.plane;
#pragma unroll
            for (int k = 0; k < 4; k++) {
                int idx = tid + k * 256;
                p4[idx] = s4[idx];
            }
        }

        if (tid == 0) {
            // all rows published long before G3 becomes resident; spin is a
            // formality for the memory-model (acquire via atomic).
            while (atomicAdd(&g_done, 0) != HW) __nanosleep(100);
            // last of the N_G3 shift CTAs resets for the next graph replay.
            int a = atomicAdd(&g_arrived, 1);
            if (a == N_G3 - 1) {
                atomicExch(&g_done, 0);
                atomicExch(&g_arrived, 0);
            }
        }
        __syncthreads();   // plane staged + sidx published

        float4* __restrict__ dst =
            (float4*)(out + ((size_t)b * COUT + CIN + cc) * HW);
        const int4* __restrict__ sidx4 = (const int4*)g_sidx;
#pragma unroll
        for (int k = 0; k < 4; k++) {
            int idx = tid + k * 256;
            int4 s = sidx4[idx];
            float4 v;
            v.x = (s.x >= 0) ? sm.plane[s.x] : 0.0f;
            v.y = (s.y >= 0) ? sm.plane[s.y] : 0.0f;
            v.z = (s.z >= 0) ? sm.plane[s.z] : 0.0f;
            v.w = (s.w >= 0) ? sm.plane[s.w] : 0.0f;
            dst[idx] = v;
        }
    }
}

// ---------------------------------------------------------------------------
extern "C" void kernel_launch(void* const* d_in, const int* in_sizes, int n_in,
                              void* d_out, int out_size) {
    const float* x    = (const float*)d_in[0];   // (8,512,64,64) f32
    const int*   mask = (const int*)d_in[1];     // (64,64) i32
    float* out = (float*)d_out;                  // (8,768,64,64) f32
    (void)in_sizes; (void)n_in; (void)out_size;

    fused_kernel<<<GRID_TOTAL, 256>>>(x, mask, out);
}

// round 17
// speedup vs baseline: 1.1902x; 1.0422x over previous
#include <cuda_runtime.h>
#include <cstdint>

// Problem: x (8,512,64,64) f32, mask (64,64) i32, out (8,768,64,64) f32
#define HW      4096
#define BATCH   8
#define CIN     512
#define C2      256
#define COUT    768

#define NSM     148
#define OCC     8
#define GRID    (NSM * OCC)        // 1184 persistent CTAs, single wave, all resident
#define NTHR    256

#define N_COPY  (BATCH * CIN)      // 4096 copy planes
#define N_SHIFT (BATCH * C2)       // 2048 shift planes

// Scratch (allocation-free rule: __device__ globals)
__device__ int g_sidx[HW];         // flag[i] ? nb[i] : -1
__device__ int g_done    = 0;      // rows published
__device__ int g_arrived = 0;      // CTAs past the wait

// ---------------------------------------------------------------------------
// threefry2x32 with key (0, 42), counters (x0=0, x1=c). JAX partitionable path:
// bits[i] = o0 ^ o1 with counter = i. ks = [0, 42, 0 ^ 42 ^ 0x1BD11BDA].
// Returns the 23-bit monotone proxy for uniform(float).
// ---------------------------------------------------------------------------
__device__ __forceinline__ unsigned threefry_bits(unsigned c) {
    const unsigned ks1 = 42u;
    const unsigned ks2 = 0x1BD11BDAu ^ 42u;   // 0x1BD11BF0
    unsigned x0 = 0u;          // counts_hi + ks0
    unsigned x1 = c + ks1;     // counts_lo + ks1
#define TF_RND(r) { x0 += x1; x1 = __funnelshift_l(x1, x1, (r)); x1 ^= x0; }
    TF_RND(13) TF_RND(15) TF_RND(26) TF_RND(6)
    x0 += ks1;  x1 += ks2 + 1u;
    TF_RND(17) TF_RND(29) TF_RND(16) TF_RND(24)
    x0 += ks2;  x1 += 0u  + 2u;
    TF_RND(13) TF_RND(15) TF_RND(26) TF_RND(6)
    x0 += 0u;   x1 += ks1 + 3u;
    TF_RND(17) TF_RND(29) TF_RND(16) TF_RND(24)
    x0 += ks1;  x1 += ks2 + 4u;
    TF_RND(13) TF_RND(15) TF_RND(26) TF_RND(6)
    x0 += ks2;  x1 += 0u  + 5u;
#undef TF_RND
    return (x0 ^ x1) >> 9;
}

// ---------------------------------------------------------------------------
// Persistent fused kernel: every CTA does argmax share -> copy share ->
// wait -> shift share. All CTAs co-resident (single wave) so the wait is
// deadlock-free and nearly free (copy phase hides it).
// ---------------------------------------------------------------------------
__global__ void __launch_bounds__(NTHR, OCC) fused_kernel(
        const float* __restrict__ x,
        const int*   __restrict__ mask,
        float*       __restrict__ out) {
    const int bid = blockIdx.x;
    const int tid = threadIdx.x;

    __shared__ union {
        struct {
            unsigned short scols[HW];  // compacted columns (ascending), 8 KB
            int wred[8];
            unsigned long long wmax[8];
        } a;
        float plane[HW];               // shift: staged source plane, 16 KB
    } sm;

    // ================= phase 1: argmax for rows bid, bid+GRID, ... ==========
    {
        // ---- mask compaction once per CTA: thread owns cols [16t,16t+16) ----
        const int lane = tid & 31;
        const int warp = tid >> 5;
        unsigned flags = 0;
        const int4* m4 = (const int4*)mask;
#pragma unroll
        for (int k = 0; k < 4; k++) {
            int4 v = m4[tid * 4 + k];
            if (v.x <= 0) flags |= 1u << (k * 4 + 0);
            if (v.y <= 0) flags |= 1u << (k * 4 + 1);
            if (v.z <= 0) flags |= 1u << (k * 4 + 2);
            if (v.w <= 0) flags |= 1u << (k * 4 + 3);
        }
        const int cnt = __popc(flags);
        int inc = cnt;
#pragma unroll
        for (int o = 1; o < 32; o <<= 1) {
            int v = __shfl_up_sync(0xFFFFFFFFu, inc, o);
            if (lane >= o) inc += v;
        }
        if (lane == 31) sm.a.wred[warp] = inc;
        __syncthreads();
        if (tid < 32) {
            int v = (tid < 8) ? sm.a.wred[tid] : 0;
#pragma unroll
            for (int o = 1; o < 8; o <<= 1) {
                int u = __shfl_up_sync(0xFFFFFFFFu, v, o);
                if (lane >= o) v += u;
            }
            if (tid < 8) sm.a.wred[tid] = v;   // inclusive warp totals
        }
        __syncthreads();
        {
            int pos = inc - cnt + (warp ? sm.a.wred[warp - 1] : 0);
            const unsigned short base = (unsigned short)(tid * 16);
#pragma unroll
            for (int k = 0; k < 16; k++) {
                if (flags & (1u << k)) sm.a.scols[pos++] = base + (unsigned short)k;
            }
        }
        __syncthreads();
        const int m = sm.a.wred[7];

        int nrows = 0;
#pragma unroll 1
        for (int row = bid; row < HW; row += GRID) {
            nrows++;
            if (mask[row] > 0) {
                const unsigned rowbase = (unsigned)row * (unsigned)HW;
                unsigned bv = 0u;
                int bj = HW - 1;     // phantom: loses to every real candidate

                int t = tid;
                for (; t + 256 < m; t += 512) {   // two independent chains
                    int j0 = sm.a.scols[t];
                    int j1 = sm.a.scols[t + 256];
                    unsigned v0 = threefry_bits(rowbase + (unsigned)j0);
                    unsigned v1 = threefry_bits(rowbase + (unsigned)j1);
                    if (v0 > bv) { bv = v0; bj = j0; }  // j0 < j1: order kept
                    if (v1 > bv) { bv = v1; bj = j1; }
                }
                if (t < m) {
                    int j = sm.a.scols[t];
                    unsigned v = threefry_bits(rowbase + (unsigned)j);
                    if (v > bv) { bv = v; bj = j; }
                }

                unsigned long long key =
                    ((unsigned long long)bv << 12) | (unsigned)(HW - 1 - bj);
#pragma unroll
                for (int o = 16; o > 0; o >>= 1) {
                    unsigned long long other = __shfl_xor_sync(0xFFFFFFFFu, key, o);
                    if (other > key) key = other;
                }
                if (lane == 0) sm.a.wmax[warp] = key;
                __syncthreads();
                if (tid < 32) {
                    unsigned long long k2 = (tid < 8) ? sm.a.wmax[tid] : 0ull;
#pragma unroll
                    for (int o = 4; o > 0; o >>= 1) {
                        unsigned long long other = __shfl_xor_sync(0xFFFFFFFFu, k2, o);
                        if (other > k2) k2 = other;
                    }
                    if (tid == 0)
                        g_sidx[row] = (m == 0) ? 0 : (HW - 1 - (int)(k2 & 0xFFFu));
                }
                __syncthreads();   // protect wmax reuse across rows
            } else {
                if (tid == 0) g_sidx[row] = -1;
            }
        }
        if (tid == 0) {
            __threadfence();
            atomicAdd(&g_done, nrows);
        }
    }

    // ================= phase 2: copy planes (hides everyone's argmax tail) ==
#pragma unroll 1
    for (int p = bid; p < N_COPY; p += GRID) {
        const int b  = p >> 9;             // /512
        const int ch = p & 511;
        const float4* __restrict__ src =
            (const float4*)(x + ((size_t)b * CIN + ch) * HW);
        float4* __restrict__ dst =
            (float4*)(out + ((size_t)b * COUT + ch) * HW);
#pragma unroll
        for (int k = 0; k < 4; k++) {
            int idx = tid + k * 256;
            dst[idx] = src[idx];
        }
    }

    // ================= phase 3: wait for all rows (normally already done) ===
    if (tid == 0) {
        while (atomicAdd(&g_done, 0) != HW) __nanosleep(100);
        // last CTA past the wait resets counters for the next graph replay
        // (all others have already observed g_done == HW).
        int a = atomicAdd(&g_arrived, 1);
        if (a == GRID - 1) {
            atomicExch(&g_done, 0);
            atomicExch(&g_arrived, 0);
        }
    }
    __syncthreads();

    // ================= phase 4: shift planes via smem-staged gather =========
#pragma unroll 1
    for (int p = bid; p < N_SHIFT; p += GRID) {
        const int b  = p >> 8;
        const int cc = p & 255;
        const float* __restrict__ src = x + ((size_t)b * CIN + C2 + cc) * HW;

        // stage source plane into smem (coalesced)
        {
            const float4* __restrict__ s4 = (const float4*)src;
            float4* __restrict__ p4 = (float4*)sm.plane;
#pragma unroll
            for (int k = 0; k < 4; k++) {
                int idx = tid + k * 256;
                p4[idx] = s4[idx];
            }
        }
        __syncthreads();

        float4* __restrict__ dst =
            (float4*)(out + ((size_t)b * COUT + CIN + cc) * HW);
        const int4* __restrict__ sidx4 = (const int4*)g_sidx;
#pragma unroll
        for (int k = 0; k < 4; k++) {
            int idx = tid + k * 256;
            int4 s = sidx4[idx];
            float4 v;
            v.x = (s.x >= 0) ? sm.plane[s.x] : 0.0f;
            v.y = (s.y >= 0) ? sm.plane[s.y] : 0.0f;
            v.z = (s.z >= 0) ? sm.plane[s.z] : 0.0f;
            v.w = (s.w >= 0) ? sm.plane[s.w] : 0.0f;
            dst[idx] = v;
        }
        __syncthreads();   // before next plane overwrites sm.plane
    }
}

// ---------------------------------------------------------------------------
extern "C" void kernel_launch(void* const* d_in, const int* in_sizes, int n_in,
                              void* d_out, int out_size) {
    const float* x    = (const float*)d_in[0];   // (8,512,64,64) f32
    const int*   mask = (const int*)d_in[1];     // (64,64) i32
    float* out = (float*)d_out;                  // (8,768,64,64) f32
    (void)in_sizes; (void)n_in; (void)out_size;

    fused_kernel<<<GRID, NTHR>>>(x, mask, out);
}